// round 8
// baseline (speedup 1.0000x reference)
#include <cuda_runtime.h>
#include <cuda_fp16.h>
#include <math.h>
#include <cstdint>

#define BATCH 8
#define SEQ   2048
#define DIM   768
#define ROWS  (BATCH * SEQ)   // 16384
#define LN_EPS 1e-5f

// ---------------------------------------------------------------------------
// Scratch (allocation-free: __device__ globals)
// ---------------------------------------------------------------------------
__device__ __half g_hn_hi[ROWS * DIM];
__device__ __half g_hn_lo[ROWS * DIM];
__device__ __half g_wqt_hi[DIM * DIM];
__device__ __half g_wqt_lo[DIM * DIM];
__device__ __half g_wkt_hi[DIM * DIM];
__device__ __half g_wkt_lo[DIM * DIM];
__device__ __half g_q_hi[ROWS * DIM];
__device__ __half g_q_lo[ROWS * DIM];
__device__ __half g_k_hi[ROWS * DIM];
__device__ __half g_k_lo[ROWS * DIM];

// ---------------------------------------------------------------------------
// PTX helpers
// ---------------------------------------------------------------------------
__device__ __forceinline__ uint32_t cvta_s(const void* p) {
    uint32_t a;
    asm("{ .reg .u64 t; cvta.to.shared.u64 t, %1; cvt.u32.u64 %0, t; }"
        : "=r"(a) : "l"(p));
    return a;
}
__device__ __forceinline__ void cp16(uint32_t dst, const void* src) {
    asm volatile("cp.async.cg.shared.global [%0], [%1], 16;" :: "r"(dst), "l"(src));
}
#define CP_COMMIT() asm volatile("cp.async.commit_group;" ::: "memory")
#define CP_WAIT0()  asm volatile("cp.async.wait_group 0;" ::: "memory")

__device__ __forceinline__ void ldm4(uint32_t& r0, uint32_t& r1, uint32_t& r2,
                                     uint32_t& r3, uint32_t addr) {
    asm volatile("ldmatrix.sync.aligned.m8n8.x4.shared.b16 {%0,%1,%2,%3}, [%4];"
                 : "=r"(r0), "=r"(r1), "=r"(r2), "=r"(r3) : "r"(addr));
}
__device__ __forceinline__ void mma16816(float* d, const uint32_t* a,
                                         uint32_t b0, uint32_t b1) {
    asm volatile(
        "mma.sync.aligned.m16n8k16.row.col.f32.f16.f16.f32 "
        "{%0,%1,%2,%3}, {%4,%5,%6,%7}, {%8,%9}, {%0,%1,%2,%3};"
        : "+f"(d[0]), "+f"(d[1]), "+f"(d[2]), "+f"(d[3])
        : "r"(a[0]), "r"(a[1]), "r"(a[2]), "r"(a[3]), "r"(b0), "r"(b1));
}

// ---------------------------------------------------------------------------
// Tiling: CTA tile 128(M) x 256(N), 512 threads (16 warps, 2x8, warp 64x32)
// Stage holds Ahi(128x32), Alo(128x32), Bhi(256x32), Blo(256x32)
// ---------------------------------------------------------------------------
#define PITCH_B   80                 // bytes per smem row (32 halfs + 16B skew)
#define A_TILE_BYTES (128 * PITCH_B) // 10240
#define B_TILE_BYTES (256 * PITCH_B) // 20480
#define OFF_AHI  0
#define OFF_ALO  A_TILE_BYTES
#define OFF_BHI  (2 * A_TILE_BYTES)
#define OFF_BLO  (2 * A_TILE_BYTES + B_TILE_BYTES)
#define STAGE_BYTES (2 * A_TILE_BYTES + 2 * B_TILE_BYTES)  // 61440
#define NSTAGE 2
#define GEMM_SMEM (NSTAGE * STAGE_BYTES)   // 122880
#define CHUNK_K 32
#define NCHUNK (DIM / CHUNK_K)     // 24
#define NTHREADS 512

// load one chunk: 3072 cp16, 6 per thread, no branches
__device__ __forceinline__ void load_chunk4(
    int c, uint32_t sbase, int tid,
    const __half* __restrict__ Ahi, const __half* __restrict__ Alo,
    const __half* __restrict__ Bhi, const __half* __restrict__ Blo,
    int arow0, int brow0)
{
    if (c >= NCHUNK) return;
    const int koff = c * CHUNK_K;
    const uint32_t st = sbase + (uint32_t)(c & 1) * STAGE_BYTES;
    const int row = tid >> 2;           // 0..127
    const int cg  = tid & 3;            // 16B group
    const uint32_t soff = (uint32_t)(row * PITCH_B + cg * 16);
    const int kcg = koff + cg * 8;

    size_t ga = (size_t)(arow0 + row) * DIM + kcg;
    cp16(st + OFF_AHI + soff, Ahi + ga);
    cp16(st + OFF_ALO + soff, Alo + ga);

    size_t gb0 = (size_t)(brow0 + row) * DIM + kcg;
    size_t gb1 = (size_t)(brow0 + 128 + row) * DIM + kcg;
    const uint32_t soff1 = soff + (uint32_t)(128 * PITCH_B);
    cp16(st + OFF_BHI + soff,  Bhi + gb0);
    cp16(st + OFF_BHI + soff1, Bhi + gb1);
    cp16(st + OFF_BLO + soff,  Blo + gb0);
    cp16(st + OFF_BLO + soff1, Blo + gb1);
}

// compute one chunk: 3 compensated terms; warp (wm 0..1, wn 0..7), tile 64x32
__device__ __forceinline__ void compute_chunk4(
    int c, uint32_t sbase, int lane, int wm, int wn, float acc[4][4][4])
{
    const uint32_t st = sbase + (uint32_t)(c & 1) * STAGE_BYTES;
    const int r16 = lane & 15;
    const int cg  = lane >> 4;
    #pragma unroll
    for (int ks = 0; ks < 2; ks++) {
        const uint32_t kso = (uint32_t)(ks * 32 + cg * 16);
        uint32_t ah[4][4], al[4][4];
        #pragma unroll
        for (int mi = 0; mi < 4; mi++) {
            int row = wm * 64 + mi * 16 + r16;
            uint32_t ad = st + (uint32_t)(row * PITCH_B) + kso;
            ldm4(ah[mi][0], ah[mi][1], ah[mi][2], ah[mi][3], ad + OFF_AHI);
            ldm4(al[mi][0], al[mi][1], al[mi][2], al[mi][3], ad + OFF_ALO);
        }
        uint32_t b[4][2];
        // ---- b_hi terms: ah*bh + al*bh ----
        #pragma unroll
        for (int nj2 = 0; nj2 < 2; nj2++) {
            int row = wn * 32 + nj2 * 16 + r16;
            uint32_t bd = st + OFF_BHI + (uint32_t)(row * PITCH_B) + kso;
            uint32_t t0, t1, t2, t3;
            ldm4(t0, t1, t2, t3, bd);
            b[nj2 * 2 + 0][0] = t0; b[nj2 * 2 + 0][1] = t2;
            b[nj2 * 2 + 1][0] = t1; b[nj2 * 2 + 1][1] = t3;
        }
        #pragma unroll
        for (int mi = 0; mi < 4; mi++)
            #pragma unroll
            for (int nj = 0; nj < 4; nj++) {
                mma16816(acc[mi][nj], ah[mi], b[nj][0], b[nj][1]);
                mma16816(acc[mi][nj], al[mi], b[nj][0], b[nj][1]);
            }
        // ---- b_lo term: ah*bl ----
        #pragma unroll
        for (int nj2 = 0; nj2 < 2; nj2++) {
            int row = wn * 32 + nj2 * 16 + r16;
            uint32_t bd = st + OFF_BLO + (uint32_t)(row * PITCH_B) + kso;
            uint32_t t0, t1, t2, t3;
            ldm4(t0, t1, t2, t3, bd);
            b[nj2 * 2 + 0][0] = t0; b[nj2 * 2 + 0][1] = t2;
            b[nj2 * 2 + 1][0] = t1; b[nj2 * 2 + 1][1] = t3;
        }
        #pragma unroll
        for (int mi = 0; mi < 4; mi++)
            #pragma unroll
            for (int nj = 0; nj < 4; nj++)
                mma16816(acc[mi][nj], ah[mi], b[nj][0], b[nj][1]);
    }
}

// ---------------------------------------------------------------------------
// 1) LayerNorm + fp16 hi/lo split
// ---------------------------------------------------------------------------
__global__ void __launch_bounds__(256) ln_split_kernel(
    const float* __restrict__ h,
    const float* __restrict__ gamma,
    const float* __restrict__ beta)
{
    const int row = blockIdx.x;
    const int tid = threadIdx.x;
    const float* x = h + (size_t)row * DIM;

    float v0 = x[tid], v1 = x[tid + 256], v2 = x[tid + 512];
    float s  = v0 + v1 + v2;
    float sq = v0 * v0 + v1 * v1 + v2 * v2;
    #pragma unroll
    for (int o = 16; o > 0; o >>= 1) {
        s  += __shfl_xor_sync(0xFFFFFFFFu, s,  o);
        sq += __shfl_xor_sync(0xFFFFFFFFu, sq, o);
    }
    __shared__ float rs[8], rq[8], stat[2];
    const int warp = tid >> 5, lane = tid & 31;
    if (lane == 0) { rs[warp] = s; rq[warp] = sq; }
    __syncthreads();
    if (tid == 0) {
        float ts = 0.f, tq = 0.f;
        #pragma unroll
        for (int i = 0; i < 8; i++) { ts += rs[i]; tq += rq[i]; }
        float mean = ts * (1.0f / DIM);
        float var  = tq * (1.0f / DIM) - mean * mean;
        stat[0] = mean;
        stat[1] = rsqrtf(var + LN_EPS);
    }
    __syncthreads();
    const float mean = stat[0], rstd = stat[1];

    size_t base = (size_t)row * DIM;
    #pragma unroll
    for (int i = 0; i < 3; i++) {
        int c = tid + i * 256;
        float v = (i == 0 ? v0 : (i == 1 ? v1 : v2));
        float y = (v - mean) * rstd * gamma[c] + beta[c];
        __half hi = __float2half_rn(y);
        __half lo = __float2half_rn(y - __half2float(hi));
        g_hn_hi[base + c] = hi;
        g_hn_lo[base + c] = lo;
    }
}

// ---------------------------------------------------------------------------
// 2) Weight transpose + split
// ---------------------------------------------------------------------------
__global__ void __launch_bounds__(256) wprep_kernel(
    const float* __restrict__ wq, const float* __restrict__ wk)
{
    __shared__ float t[32][33];
    const float* W = blockIdx.z ? wk : wq;
    __half* Whi = blockIdx.z ? g_wkt_hi : g_wqt_hi;
    __half* Wlo = blockIdx.z ? g_wkt_lo : g_wqt_lo;
    const int x0 = blockIdx.x * 32, y0 = blockIdx.y * 32;
    const int tx = threadIdx.x, ty = threadIdx.y;

    for (int j = ty; j < 32; j += 8)
        t[j][tx] = W[(size_t)(y0 + j) * DIM + x0 + tx];
    __syncthreads();
    for (int j = ty; j < 32; j += 8) {
        float v = t[tx][j];
        __half hi = __float2half_rn(v);
        __half lo = __float2half_rn(v - __half2float(hi));
        size_t o = (size_t)(x0 + j) * DIM + y0 + tx;
        Whi[o] = hi;
        Wlo[o] = lo;
    }
}

// ---------------------------------------------------------------------------
// 3a) Merged Q+K projections: grid (6, 128); bx<3 -> q, else k
// ---------------------------------------------------------------------------
__global__ void __launch_bounds__(NTHREADS, 1) gemm_proj(const float* __restrict__ bq,
                                                         const float* __restrict__ bk)
{
    extern __shared__ __align__(16) char smem[];
    const uint32_t sbase = cvta_s(smem);
    const int tid = threadIdx.x;
    const int wid = tid >> 5, lane = tid & 31;
    const int wm = wid >> 3, wn = wid & 7;

    const bool isK  = blockIdx.x >= 3;
    const int  nb   = isK ? (int)blockIdx.x - 3 : (int)blockIdx.x;
    const int arow0 = blockIdx.y * 128;
    const int brow0 = nb * 256;

    const __half* Bhi = isK ? g_wkt_hi : g_wqt_hi;
    const __half* Blo = isK ? g_wkt_lo : g_wqt_lo;
    const float*  bias = isK ? bk : bq;
    __half* outHi = isK ? g_k_hi : g_q_hi;
    __half* outLo = isK ? g_k_lo : g_q_lo;

    float acc[4][4][4] = {};

    load_chunk4(0, sbase, tid, g_hn_hi, g_hn_lo, Bhi, Blo, arow0, brow0);
    CP_COMMIT();
    for (int c = 0; c < NCHUNK; c++) {
        CP_WAIT0();
        __syncthreads();
        load_chunk4(c + 1, sbase, tid, g_hn_hi, g_hn_lo, Bhi, Blo, arow0, brow0);
        CP_COMMIT();
        compute_chunk4(c, sbase, lane, wm, wn, acc);
    }

    const int rbase = arow0 + wm * 64 + (lane >> 2);
    const int cbase = nb * 256 + wn * 32 + (lane & 3) * 2;
    #pragma unroll
    for (int mi = 0; mi < 4; mi++) {
        #pragma unroll
        for (int hm = 0; hm < 2; hm++) {
            const int r = rbase + mi * 16 + hm * 8;
            #pragma unroll
            for (int nj = 0; nj < 4; nj++) {
                const int cc = cbase + nj * 8;
                float v0 = acc[mi][nj][hm * 2 + 0] + bias[cc];
                float v1 = acc[mi][nj][hm * 2 + 1] + bias[cc + 1];
                __half h0 = __float2half_rn(v0);
                __half h1 = __float2half_rn(v1);
                __half l0 = __float2half_rn(v0 - __half2float(h0));
                __half l1 = __float2half_rn(v1 - __half2float(h1));
                size_t o = (size_t)r * DIM + cc;
                *(__half2*)&outHi[o] = __halves2half2(h0, h1);
                *(__half2*)&outLo[o] = __halves2half2(l0, l1);
            }
        }
    }
}

// ---------------------------------------------------------------------------
// 3b) Scores GEMM: grid (8, 16, 8); N block 256
// ---------------------------------------------------------------------------
__global__ void __launch_bounds__(NTHREADS, 1) gemm_scores(float* __restrict__ outF)
{
    extern __shared__ __align__(16) char smem[];
    const uint32_t sbase = cvta_s(smem);
    const int tid = threadIdx.x;
    const int wid = tid >> 5, lane = tid & 31;
    const int wm = wid >> 3, wn = wid & 7;

    const int arow0 = blockIdx.z * SEQ + blockIdx.y * 128;
    const int brow0 = blockIdx.z * SEQ + blockIdx.x * 256;

    float acc[4][4][4] = {};

    load_chunk4(0, sbase, tid, g_q_hi, g_q_lo, g_k_hi, g_k_lo, arow0, brow0);
    CP_COMMIT();
    for (int c = 0; c < NCHUNK; c++) {
        CP_WAIT0();
        __syncthreads();
        load_chunk4(c + 1, sbase, tid, g_q_hi, g_q_lo, g_k_hi, g_k_lo, arow0, brow0);
        CP_COMMIT();
        compute_chunk4(c, sbase, lane, wm, wn, acc);
    }

    const int rbase = arow0 + wm * 64 + (lane >> 2);
    const int cbase = blockIdx.x * 256 + wn * 32 + (lane & 3) * 2;
    #pragma unroll
    for (int mi = 0; mi < 4; mi++) {
        #pragma unroll
        for (int hm = 0; hm < 2; hm++) {
            const int r = rbase + mi * 16 + hm * 8;
            #pragma unroll
            for (int nj = 0; nj < 4; nj++) {
                const int cc = cbase + nj * 8;
                float2 v;
                v.x = acc[mi][nj][hm * 2 + 0];
                v.y = acc[mi][nj][hm * 2 + 1];
                *(float2*)&outF[(size_t)r * SEQ + cc] = v;
            }
        }
    }
}

// ---------------------------------------------------------------------------
// 4) Row softmax over 2048 columns
// ---------------------------------------------------------------------------
__global__ void __launch_bounds__(256) softmax_kernel(float* __restrict__ data)
{
    const size_t row = blockIdx.x;
    float* p = data + row * (size_t)SEQ;
    const int tid = threadIdx.x;

    float v[8];
    float mx = -INFINITY;
    #pragma unroll
    for (int i = 0; i < 8; i++) {
        v[i] = p[i * 256 + tid];
        mx = fmaxf(mx, v[i]);
    }
    #pragma unroll
    for (int o = 16; o > 0; o >>= 1)
        mx = fmaxf(mx, __shfl_xor_sync(0xFFFFFFFFu, mx, o));

    __shared__ float sm[8], ss[8];
    const int warp = tid >> 5, lane = tid & 31;
    if (lane == 0) sm[warp] = mx;
    __syncthreads();
    float m = sm[0];
    #pragma unroll
    for (int i = 1; i < 8; i++) m = fmaxf(m, sm[i]);

    float s = 0.f;
    #pragma unroll
    for (int i = 0; i < 8; i++) { v[i] = expf(v[i] - m); s += v[i]; }
    #pragma unroll
    for (int o = 16; o > 0; o >>= 1)
        s += __shfl_xor_sync(0xFFFFFFFFu, s, o);
    if (lane == 0) ss[warp] = s;
    __syncthreads();
    float tot = 0.f;
    #pragma unroll
    for (int i = 0; i < 8; i++) tot += ss[i];
    const float inv = 1.0f / tot;

    #pragma unroll
    for (int i = 0; i < 8; i++)
        p[i * 256 + tid] = v[i] * inv;
}

// ---------------------------------------------------------------------------
// Launcher
// ---------------------------------------------------------------------------
extern "C" void kernel_launch(void* const* d_in, const int* in_sizes, int n_in,
                              void* d_out, int out_size)
{
    const float* h     = (const float*)d_in[0];
    const float* gamma = (const float*)d_in[1];
    const float* beta  = (const float*)d_in[2];
    const float* wq    = (const float*)d_in[3];
    const float* bq    = (const float*)d_in[4];
    const float* wk    = (const float*)d_in[5];
    const float* bk    = (const float*)d_in[6];
    float* out = (float*)d_out;

    cudaFuncSetAttribute(gemm_proj,   cudaFuncAttributeMaxDynamicSharedMemorySize, GEMM_SMEM);
    cudaFuncSetAttribute(gemm_scores, cudaFuncAttributeMaxDynamicSharedMemorySize, GEMM_SMEM);

    // 1) LayerNorm + split
    ln_split_kernel<<<ROWS, 256>>>(h, gamma, beta);

    // 2) Weight transpose + split
    wprep_kernel<<<dim3(24, 24, 2), dim3(32, 8)>>>(wq, wk);

    // 3) Merged Q+K projections (tile 128x256)
    gemm_proj<<<dim3(6, ROWS / 128), NTHREADS, GEMM_SMEM>>>(bq, bk);

    // 4) Scores (tile 128x256)
    gemm_scores<<<dim3(SEQ / 256, SEQ / 128, BATCH), NTHREADS, GEMM_SMEM>>>(out);

    // 5) Softmax in place
    softmax_kernel<<<ROWS, 256>>>(out);
}

// round 10
// speedup vs baseline: 1.1538x; 1.1538x over previous
#include <cuda_runtime.h>
#include <cuda_fp16.h>
#include <math.h>
#include <cstdint>

#define BATCH 8
#define SEQ   2048
#define DIM   768
#define ROWS  (BATCH * SEQ)   // 16384
#define LN_EPS 1e-5f

// ---------------------------------------------------------------------------
// Scratch (allocation-free: __device__ globals)
// ---------------------------------------------------------------------------
__device__ __half g_hn_hi[ROWS * DIM];
__device__ __half g_hn_lo[ROWS * DIM];
__device__ __half g_wqt_hi[DIM * DIM];
__device__ __half g_wqt_lo[DIM * DIM];
__device__ __half g_wkt_hi[DIM * DIM];
__device__ __half g_wkt_lo[DIM * DIM];
__device__ __half g_q_hi[ROWS * DIM];
__device__ __half g_q_lo[ROWS * DIM];
__device__ __half g_k_hi[ROWS * DIM];
__device__ __half g_k_lo[ROWS * DIM];

// ---------------------------------------------------------------------------
// PTX helpers
// ---------------------------------------------------------------------------
__device__ __forceinline__ uint32_t cvta_s(const void* p) {
    uint32_t a;
    asm("{ .reg .u64 t; cvta.to.shared.u64 t, %1; cvt.u32.u64 %0, t; }"
        : "=r"(a) : "l"(p));
    return a;
}
__device__ __forceinline__ void cp16(uint32_t dst, const void* src) {
    asm volatile("cp.async.cg.shared.global [%0], [%1], 16;" :: "r"(dst), "l"(src));
}
#define CP_COMMIT() asm volatile("cp.async.commit_group;" ::: "memory")
#define CP_WAIT0()  asm volatile("cp.async.wait_group 0;" ::: "memory")

__device__ __forceinline__ void ldm4(uint32_t& r0, uint32_t& r1, uint32_t& r2,
                                     uint32_t& r3, uint32_t addr) {
    asm volatile("ldmatrix.sync.aligned.m8n8.x4.shared.b16 {%0,%1,%2,%3}, [%4];"
                 : "=r"(r0), "=r"(r1), "=r"(r2), "=r"(r3) : "r"(addr));
}
__device__ __forceinline__ void mma16816(float* d, const uint32_t* a,
                                         uint32_t b0, uint32_t b1) {
    asm volatile(
        "mma.sync.aligned.m16n8k16.row.col.f32.f16.f16.f32 "
        "{%0,%1,%2,%3}, {%4,%5,%6,%7}, {%8,%9}, {%0,%1,%2,%3};"
        : "+f"(d[0]), "+f"(d[1]), "+f"(d[2]), "+f"(d[3])
        : "r"(a[0]), "r"(a[1]), "r"(a[2]), "r"(a[3]), "r"(b0), "r"(b1));
}

// ---------------------------------------------------------------------------
// Tiling: CTA tile 128x128, 256 threads (8 warps, 2x4, warp 64x32)
// Stage = Ahi, Alo, Bhi, Blo tiles of 128x32 halfs each
// ---------------------------------------------------------------------------
#define PITCH_B   80               // bytes per smem row (32 halfs + 16B skew)
#define OP_BYTES  (128 * PITCH_B)  // 10240 per operand tile
#define OFF_AHI  0
#define OFF_ALO  OP_BYTES
#define OFF_BHI  (2 * OP_BYTES)
#define OFF_BLO  (3 * OP_BYTES)
#define STAGE_BYTES (4 * OP_BYTES) // 40960
#define NSTAGE 2
#define GEMM_SMEM (NSTAGE * STAGE_BYTES)   // 81920
#define CHUNK_K 32
#define NCHUNK (DIM / CHUNK_K)     // 24
#define ROW1_S (64 * PITCH_B)      // smem offset of row+64
#define ROW1_G ((size_t)64 * DIM)  // gmem offset of row+64

// ---------------------------------------------------------------------------
// compute one chunk at compile-known stage base (per-chunk 3-term passes)
// ---------------------------------------------------------------------------
__device__ __forceinline__ void compute_chunk4(
    uint32_t st, int lane, int wm, int wn, float acc[4][4][4])
{
    const int r16 = lane & 15;
    const int cg  = lane >> 4;
    #pragma unroll
    for (int ks = 0; ks < 2; ks++) {
        const uint32_t kso = (uint32_t)(ks * 32 + cg * 16);
        uint32_t ah[4][4], al[4][4];
        #pragma unroll
        for (int mi = 0; mi < 4; mi++) {
            int row = wm * 64 + mi * 16 + r16;
            uint32_t ad = st + (uint32_t)(row * PITCH_B) + kso;
            ldm4(ah[mi][0], ah[mi][1], ah[mi][2], ah[mi][3], ad + OFF_AHI);
            ldm4(al[mi][0], al[mi][1], al[mi][2], al[mi][3], ad + OFF_ALO);
        }
        uint32_t b[4][2];
        // ---- b_hi terms: ah*bh + al*bh ----
        #pragma unroll
        for (int nj2 = 0; nj2 < 2; nj2++) {
            int row = wn * 32 + nj2 * 16 + r16;
            uint32_t bd = st + OFF_BHI + (uint32_t)(row * PITCH_B) + kso;
            uint32_t t0, t1, t2, t3;
            ldm4(t0, t1, t2, t3, bd);
            b[nj2 * 2 + 0][0] = t0; b[nj2 * 2 + 0][1] = t2;
            b[nj2 * 2 + 1][0] = t1; b[nj2 * 2 + 1][1] = t3;
        }
        #pragma unroll
        for (int mi = 0; mi < 4; mi++)
            #pragma unroll
            for (int nj = 0; nj < 4; nj++) {
                mma16816(acc[mi][nj], ah[mi], b[nj][0], b[nj][1]);
                mma16816(acc[mi][nj], al[mi], b[nj][0], b[nj][1]);
            }
        // ---- b_lo term: ah*bl ----
        #pragma unroll
        for (int nj2 = 0; nj2 < 2; nj2++) {
            int row = wn * 32 + nj2 * 16 + r16;
            uint32_t bd = st + OFF_BLO + (uint32_t)(row * PITCH_B) + kso;
            uint32_t t0, t1, t2, t3;
            ldm4(t0, t1, t2, t3, bd);
            b[nj2 * 2 + 0][0] = t0; b[nj2 * 2 + 0][1] = t2;
            b[nj2 * 2 + 1][0] = t1; b[nj2 * 2 + 1][1] = t3;
        }
        #pragma unroll
        for (int mi = 0; mi < 4; mi++)
            #pragma unroll
            for (int nj = 0; nj < 4; nj++)
                mma16816(acc[mi][nj], ah[mi], b[nj][0], b[nj][1]);
    }
}

// ---------------------------------------------------------------------------
// GEMM core shared by proj/scores: induction-pointer loader + unrolled-by-2
// pipeline. Templated on epilogue via mode flag at call sites.
// ---------------------------------------------------------------------------
struct LoaderState {
    const __half *pAhi, *pAlo, *pBhi, *pBlo;   // per-thread gmem ptrs
    uint32_t sA, sB;                           // per-thread smem offsets in stage
};

__device__ __forceinline__ LoaderState make_loader(
    int tid, const __half* Ahi, const __half* Alo,
    const __half* Bhi, const __half* Blo, int arow0, int brow0)
{
    LoaderState L;
    const int row = tid >> 2;           // 0..63
    const int cg  = tid & 3;
    size_t ga = (size_t)(arow0 + row) * DIM + cg * 8;
    size_t gb = (size_t)(brow0 + row) * DIM + cg * 8;
    L.pAhi = Ahi + ga; L.pAlo = Alo + ga;
    L.pBhi = Bhi + gb; L.pBlo = Blo + gb;
    L.sA = (uint32_t)(row * PITCH_B + cg * 16);
    L.sB = L.sA;
    return L;
}

// issue one chunk into stage base st; advance pointers by CHUNK_K
__device__ __forceinline__ void issue_chunk(LoaderState& L, uint32_t st)
{
    cp16(st + OFF_AHI + L.sA,          L.pAhi);
    cp16(st + OFF_AHI + L.sA + ROW1_S, L.pAhi + ROW1_G);
    cp16(st + OFF_ALO + L.sA,          L.pAlo);
    cp16(st + OFF_ALO + L.sA + ROW1_S, L.pAlo + ROW1_G);
    cp16(st + OFF_BHI + L.sB,          L.pBhi);
    cp16(st + OFF_BHI + L.sB + ROW1_S, L.pBhi + ROW1_G);
    cp16(st + OFF_BLO + L.sB,          L.pBlo);
    cp16(st + OFF_BLO + L.sB + ROW1_S, L.pBlo + ROW1_G);
    L.pAhi += CHUNK_K; L.pAlo += CHUNK_K;
    L.pBhi += CHUNK_K; L.pBlo += CHUNK_K;
}

// full mainloop: 24 chunks, stages compile-time, 2-deep cp.async pipeline
__device__ __forceinline__ void gemm_mainloop(
    LoaderState& L, uint32_t s0, int lane, int wm, int wn, float acc[4][4][4])
{
    const uint32_t s1 = s0 + STAGE_BYTES;
    issue_chunk(L, s0); CP_COMMIT();
    #pragma unroll 1
    for (int c = 0; c < NCHUNK; c += 2) {
        CP_WAIT0();
        __syncthreads();
        if (c + 1 < NCHUNK) { issue_chunk(L, s1); CP_COMMIT(); }
        compute_chunk4(s0, lane, wm, wn, acc);
        CP_WAIT0();
        __syncthreads();
        if (c + 2 < NCHUNK) { issue_chunk(L, s0); CP_COMMIT(); }
        compute_chunk4(s1, lane, wm, wn, acc);
    }
}

// ---------------------------------------------------------------------------
// 1) LayerNorm + fp16 hi/lo split
// ---------------------------------------------------------------------------
__global__ void __launch_bounds__(256) ln_split_kernel(
    const float* __restrict__ h,
    const float* __restrict__ gamma,
    const float* __restrict__ beta)
{
    const int row = blockIdx.x;
    const int tid = threadIdx.x;
    const float* x = h + (size_t)row * DIM;

    float v0 = x[tid], v1 = x[tid + 256], v2 = x[tid + 512];
    float s  = v0 + v1 + v2;
    float sq = v0 * v0 + v1 * v1 + v2 * v2;
    #pragma unroll
    for (int o = 16; o > 0; o >>= 1) {
        s  += __shfl_xor_sync(0xFFFFFFFFu, s,  o);
        sq += __shfl_xor_sync(0xFFFFFFFFu, sq, o);
    }
    __shared__ float rs[8], rq[8], stat[2];
    const int warp = tid >> 5, lane = tid & 31;
    if (lane == 0) { rs[warp] = s; rq[warp] = sq; }
    __syncthreads();
    if (tid == 0) {
        float ts = 0.f, tq = 0.f;
        #pragma unroll
        for (int i = 0; i < 8; i++) { ts += rs[i]; tq += rq[i]; }
        float mean = ts * (1.0f / DIM);
        float var  = tq * (1.0f / DIM) - mean * mean;
        stat[0] = mean;
        stat[1] = rsqrtf(var + LN_EPS);
    }
    __syncthreads();
    const float mean = stat[0], rstd = stat[1];

    size_t base = (size_t)row * DIM;
    #pragma unroll
    for (int i = 0; i < 3; i++) {
        int c = tid + i * 256;
        float v = (i == 0 ? v0 : (i == 1 ? v1 : v2));
        float y = (v - mean) * rstd * gamma[c] + beta[c];
        __half hi = __float2half_rn(y);
        __half lo = __float2half_rn(y - __half2float(hi));
        g_hn_hi[base + c] = hi;
        g_hn_lo[base + c] = lo;
    }
}

// ---------------------------------------------------------------------------
// 2) Weight transpose + split
// ---------------------------------------------------------------------------
__global__ void __launch_bounds__(256) wprep_kernel(
    const float* __restrict__ wq, const float* __restrict__ wk)
{
    __shared__ float t[32][33];
    const float* W = blockIdx.z ? wk : wq;
    __half* Whi = blockIdx.z ? g_wkt_hi : g_wqt_hi;
    __half* Wlo = blockIdx.z ? g_wkt_lo : g_wqt_lo;
    const int x0 = blockIdx.x * 32, y0 = blockIdx.y * 32;
    const int tx = threadIdx.x, ty = threadIdx.y;

    for (int j = ty; j < 32; j += 8)
        t[j][tx] = W[(size_t)(y0 + j) * DIM + x0 + tx];
    __syncthreads();
    for (int j = ty; j < 32; j += 8) {
        float v = t[tx][j];
        __half hi = __float2half_rn(v);
        __half lo = __float2half_rn(v - __half2float(hi));
        size_t o = (size_t)(x0 + j) * DIM + y0 + tx;
        Whi[o] = hi;
        Wlo[o] = lo;
    }
}

// ---------------------------------------------------------------------------
// 3a) Merged Q+K projections: grid (12, 128); bx<6 -> q, else k
// ---------------------------------------------------------------------------
__global__ void __launch_bounds__(256, 2) gemm_proj(const float* __restrict__ bq,
                                                    const float* __restrict__ bk)
{
    extern __shared__ __align__(16) char smem[];
    const uint32_t sbase = cvta_s(smem);
    const int tid = threadIdx.x;
    const int wid = tid >> 5, lane = tid & 31;
    const int wm = wid >> 2, wn = wid & 3;

    const bool isK  = blockIdx.x >= 6;
    const int  nb   = isK ? (int)blockIdx.x - 6 : (int)blockIdx.x;
    const int arow0 = blockIdx.y * 128;
    const int brow0 = nb * 128;

    const __half* Bhi = isK ? g_wkt_hi : g_wqt_hi;
    const __half* Blo = isK ? g_wkt_lo : g_wqt_lo;
    const float*  bias = isK ? bk : bq;
    __half* outHi = isK ? g_k_hi : g_q_hi;
    __half* outLo = isK ? g_k_lo : g_q_lo;

    float acc[4][4][4] = {};
    LoaderState L = make_loader(tid, g_hn_hi, g_hn_lo, Bhi, Blo, arow0, brow0);
    gemm_mainloop(L, sbase, lane, wm, wn, acc);

    const int rbase = arow0 + wm * 64 + (lane >> 2);
    const int cbase = nb * 128 + wn * 32 + (lane & 3) * 2;
    #pragma unroll
    for (int mi = 0; mi < 4; mi++) {
        #pragma unroll
        for (int hm = 0; hm < 2; hm++) {
            const int r = rbase + mi * 16 + hm * 8;
            #pragma unroll
            for (int nj = 0; nj < 4; nj++) {
                const int cc = cbase + nj * 8;
                float v0 = acc[mi][nj][hm * 2 + 0] + bias[cc];
                float v1 = acc[mi][nj][hm * 2 + 1] + bias[cc + 1];
                __half h0 = __float2half_rn(v0);
                __half h1 = __float2half_rn(v1);
                __half l0 = __float2half_rn(v0 - __half2float(h0));
                __half l1 = __float2half_rn(v1 - __half2float(h1));
                size_t o = (size_t)r * DIM + cc;
                *(__half2*)&outHi[o] = __halves2half2(h0, h1);
                *(__half2*)&outLo[o] = __halves2half2(l0, l1);
            }
        }
    }
}

// ---------------------------------------------------------------------------
// 3b) Scores GEMM: grid (16, 16, 8)
// ---------------------------------------------------------------------------
__global__ void __launch_bounds__(256, 2) gemm_scores(float* __restrict__ outF)
{
    extern __shared__ __align__(16) char smem[];
    const uint32_t sbase = cvta_s(smem);
    const int tid = threadIdx.x;
    const int wid = tid >> 5, lane = tid & 31;
    const int wm = wid >> 2, wn = wid & 3;

    const int arow0 = blockIdx.z * SEQ + blockIdx.y * 128;
    const int brow0 = blockIdx.z * SEQ + blockIdx.x * 128;

    float acc[4][4][4] = {};
    LoaderState L = make_loader(tid, g_q_hi, g_q_lo, g_k_hi, g_k_lo, arow0, brow0);
    gemm_mainloop(L, sbase, lane, wm, wn, acc);

    const int rbase = arow0 + wm * 64 + (lane >> 2);
    const int cbase = blockIdx.x * 128 + wn * 32 + (lane & 3) * 2;
    #pragma unroll
    for (int mi = 0; mi < 4; mi++) {
        #pragma unroll
        for (int hm = 0; hm < 2; hm++) {
            const int r = rbase + mi * 16 + hm * 8;
            #pragma unroll
            for (int nj = 0; nj < 4; nj++) {
                const int cc = cbase + nj * 8;
                float2 v;
                v.x = acc[mi][nj][hm * 2 + 0];
                v.y = acc[mi][nj][hm * 2 + 1];
                *(float2*)&outF[(size_t)r * SEQ + cc] = v;
            }
        }
    }
}

// ---------------------------------------------------------------------------
// 4) Row softmax over 2048 columns
// ---------------------------------------------------------------------------
__global__ void __launch_bounds__(256) softmax_kernel(float* __restrict__ data)
{
    const size_t row = blockIdx.x;
    float* p = data + row * (size_t)SEQ;
    const int tid = threadIdx.x;

    float v[8];
    float mx = -INFINITY;
    #pragma unroll
    for (int i = 0; i < 8; i++) {
        v[i] = p[i * 256 + tid];
        mx = fmaxf(mx, v[i]);
    }
    #pragma unroll
    for (int o = 16; o > 0; o >>= 1)
        mx = fmaxf(mx, __shfl_xor_sync(0xFFFFFFFFu, mx, o));

    __shared__ float sm[8], ss[8];
    const int warp = tid >> 5, lane = tid & 31;
    if (lane == 0) sm[warp] = mx;
    __syncthreads();
    float m = sm[0];
    #pragma unroll
    for (int i = 1; i < 8; i++) m = fmaxf(m, sm[i]);

    float s = 0.f;
    #pragma unroll
    for (int i = 0; i < 8; i++) { v[i] = expf(v[i] - m); s += v[i]; }
    #pragma unroll
    for (int o = 16; o > 0; o >>= 1)
        s += __shfl_xor_sync(0xFFFFFFFFu, s, o);
    if (lane == 0) ss[warp] = s;
    __syncthreads();
    float tot = 0.f;
    #pragma unroll
    for (int i = 0; i < 8; i++) tot += ss[i];
    const float inv = 1.0f / tot;

    #pragma unroll
    for (int i = 0; i < 8; i++)
        p[i * 256 + tid] = v[i] * inv;
}

// ---------------------------------------------------------------------------
// Launcher
// ---------------------------------------------------------------------------
extern "C" void kernel_launch(void* const* d_in, const int* in_sizes, int n_in,
                              void* d_out, int out_size)
{
    const float* h     = (const float*)d_in[0];
    const float* gamma = (const float*)d_in[1];
    const float* beta  = (const float*)d_in[2];
    const float* wq    = (const float*)d_in[3];
    const float* bq    = (const float*)d_in[4];
    const float* wk    = (const float*)d_in[5];
    const float* bk    = (const float*)d_in[6];
    float* out = (float*)d_out;

    cudaFuncSetAttribute(gemm_proj,   cudaFuncAttributeMaxDynamicSharedMemorySize, GEMM_SMEM);
    cudaFuncSetAttribute(gemm_scores, cudaFuncAttributeMaxDynamicSharedMemorySize, GEMM_SMEM);

    // 1) LayerNorm + split
    ln_split_kernel<<<ROWS, 256>>>(h, gamma, beta);

    // 2) Weight transpose + split
    wprep_kernel<<<dim3(24, 24, 2), dim3(32, 8)>>>(wq, wk);

    // 3) Merged Q+K projections (tile 128x128, 2 CTAs/SM)
    gemm_proj<<<dim3(12, ROWS / 128), 256, GEMM_SMEM>>>(bq, bk);

    // 4) Scores (tile 128x128, 2 CTAs/SM)
    gemm_scores<<<dim3(SEQ / 128, SEQ / 128, BATCH), 256, GEMM_SMEM>>>(out);

    // 5) Softmax in place
    softmax_kernel<<<ROWS, 256>>>(out);
}

// round 11
// speedup vs baseline: 1.2709x; 1.1015x over previous
#include <cuda_runtime.h>
#include <cuda_fp16.h>
#include <math.h>
#include <cstdint>

#define BATCH 8
#define SEQ   2048
#define DIM   768
#define ROWS  (BATCH * SEQ)   // 16384
#define LN_EPS 1e-5f

// ---------------------------------------------------------------------------
// Scratch (allocation-free: __device__ globals)
// ---------------------------------------------------------------------------
__device__ __half g_hn_hi[ROWS * DIM];
__device__ __half g_hn_lo[ROWS * DIM];
__device__ __half g_wqt_hi[DIM * DIM];
__device__ __half g_wqt_lo[DIM * DIM];
__device__ __half g_wkt_hi[DIM * DIM];
__device__ __half g_wkt_lo[DIM * DIM];
__device__ __half g_q_hi[ROWS * DIM];
__device__ __half g_q_lo[ROWS * DIM];
__device__ __half g_k_hi[ROWS * DIM];
__device__ __half g_k_lo[ROWS * DIM];

// ---------------------------------------------------------------------------
// PTX helpers
// ---------------------------------------------------------------------------
__device__ __forceinline__ uint32_t cvta_s(const void* p) {
    uint32_t a;
    asm("{ .reg .u64 t; cvta.to.shared.u64 t, %1; cvt.u32.u64 %0, t; }"
        : "=r"(a) : "l"(p));
    return a;
}
__device__ __forceinline__ void cp16(uint32_t dst, const void* src) {
    asm volatile("cp.async.cg.shared.global [%0], [%1], 16;" :: "r"(dst), "l"(src));
}
#define CP_COMMIT()  asm volatile("cp.async.commit_group;" ::: "memory")
#define CP_WAITG1()  asm volatile("cp.async.wait_group 1;" ::: "memory")

__device__ __forceinline__ void ldm4(uint32_t& r0, uint32_t& r1, uint32_t& r2,
                                     uint32_t& r3, uint32_t addr) {
    asm volatile("ldmatrix.sync.aligned.m8n8.x4.shared.b16 {%0,%1,%2,%3}, [%4];"
                 : "=r"(r0), "=r"(r1), "=r"(r2), "=r"(r3) : "r"(addr));
}
__device__ __forceinline__ void mma16816(float* d, const uint32_t* a,
                                         uint32_t b0, uint32_t b1) {
    asm volatile(
        "mma.sync.aligned.m16n8k16.row.col.f32.f16.f16.f32 "
        "{%0,%1,%2,%3}, {%4,%5,%6,%7}, {%8,%9}, {%0,%1,%2,%3};"
        : "+f"(d[0]), "+f"(d[1]), "+f"(d[2]), "+f"(d[3])
        : "r"(a[0]), "r"(a[1]), "r"(a[2]), "r"(a[3]), "r"(b0), "r"(b1));
}

// ---------------------------------------------------------------------------
// Tiling: CTA 128x128, 256 thr (8 warps 2x4, warp 64x32)
// Stage = Ahi, Alo, Bhi, Blo tiles of 128x32 halfs, PITCH 64B + XOR swizzle
//   smem 16B-col c' = c ^ ((row>>1)&3)   (conflict-free ldmatrix + stores,
//   invariant under row+64)
// ---------------------------------------------------------------------------
#define PITCH_B   64
#define OP_BYTES  (128 * PITCH_B)  // 8192
#define OFF_AHI  0
#define OFF_ALO  OP_BYTES
#define OFF_BHI  (2 * OP_BYTES)
#define OFF_BLO  (3 * OP_BYTES)
#define STAGE_BYTES (4 * OP_BYTES) // 32768
#define NSTAGE 3
#define GEMM_SMEM (NSTAGE * STAGE_BYTES)   // 98304
#define CHUNK_K 32
#define NCHUNK (DIM / CHUNK_K)     // 24
#define ROW1_S (64 * PITCH_B)      // smem offset of row+64
#define ROW1_G ((size_t)64 * DIM)  // gmem offset of row+64

// ---------------------------------------------------------------------------
// compute one chunk at compile-known stage base (3 compensated terms)
// ---------------------------------------------------------------------------
__device__ __forceinline__ void compute_chunk4(
    uint32_t st, int lane, int wm, int wn, float acc[4][4][4])
{
    const int r16 = lane & 15;
    const int cg  = lane >> 4;
    const int sw  = (r16 >> 1) & 3;
    #pragma unroll
    for (int ks = 0; ks < 2; ks++) {
        const uint32_t kswz = (uint32_t)((((ks * 2 + cg) ^ sw) & 3) * 16);
        uint32_t ah[4][4], al[4][4];
        #pragma unroll
        for (int mi = 0; mi < 4; mi++) {
            int row = wm * 64 + mi * 16 + r16;
            uint32_t ad = st + (uint32_t)(row * PITCH_B) + kswz;
            ldm4(ah[mi][0], ah[mi][1], ah[mi][2], ah[mi][3], ad + OFF_AHI);
            ldm4(al[mi][0], al[mi][1], al[mi][2], al[mi][3], ad + OFF_ALO);
        }
        uint32_t b[4][2];
        // ---- b_hi terms: ah*bh + al*bh ----
        #pragma unroll
        for (int nj2 = 0; nj2 < 2; nj2++) {
            int row = wn * 32 + nj2 * 16 + r16;
            uint32_t bd = st + OFF_BHI + (uint32_t)(row * PITCH_B) + kswz;
            uint32_t t0, t1, t2, t3;
            ldm4(t0, t1, t2, t3, bd);
            b[nj2 * 2 + 0][0] = t0; b[nj2 * 2 + 0][1] = t2;
            b[nj2 * 2 + 1][0] = t1; b[nj2 * 2 + 1][1] = t3;
        }
        #pragma unroll
        for (int mi = 0; mi < 4; mi++)
            #pragma unroll
            for (int nj = 0; nj < 4; nj++) {
                mma16816(acc[mi][nj], ah[mi], b[nj][0], b[nj][1]);
                mma16816(acc[mi][nj], al[mi], b[nj][0], b[nj][1]);
            }
        // ---- b_lo term: ah*bl ----
        #pragma unroll
        for (int nj2 = 0; nj2 < 2; nj2++) {
            int row = wn * 32 + nj2 * 16 + r16;
            uint32_t bd = st + OFF_BLO + (uint32_t)(row * PITCH_B) + kswz;
            uint32_t t0, t1, t2, t3;
            ldm4(t0, t1, t2, t3, bd);
            b[nj2 * 2 + 0][0] = t0; b[nj2 * 2 + 0][1] = t2;
            b[nj2 * 2 + 1][0] = t1; b[nj2 * 2 + 1][1] = t3;
        }
        #pragma unroll
        for (int mi = 0; mi < 4; mi++)
            #pragma unroll
            for (int nj = 0; nj < 4; nj++)
                mma16816(acc[mi][nj], ah[mi], b[nj][0], b[nj][1]);
    }
}

// ---------------------------------------------------------------------------
// Loader: induction pointers; smem offset carries the XOR swizzle
// ---------------------------------------------------------------------------
struct LoaderState {
    const __half *pAhi, *pAlo, *pBhi, *pBlo;
    uint32_t sA;
};

__device__ __forceinline__ LoaderState make_loader(
    int tid, const __half* Ahi, const __half* Alo,
    const __half* Bhi, const __half* Blo, int arow0, int brow0)
{
    LoaderState L;
    const int row = tid >> 2;           // 0..63
    const int c   = tid & 3;            // 16B data col
    const int cs  = c ^ ((row >> 1) & 3);
    size_t ga = (size_t)(arow0 + row) * DIM + c * 8;
    size_t gb = (size_t)(brow0 + row) * DIM + c * 8;
    L.pAhi = Ahi + ga; L.pAlo = Alo + ga;
    L.pBhi = Bhi + gb; L.pBlo = Blo + gb;
    L.sA = (uint32_t)(row * PITCH_B + cs * 16);
    return L;
}

__device__ __forceinline__ void issue_chunk(LoaderState& L, uint32_t st)
{
    cp16(st + OFF_AHI + L.sA,          L.pAhi);
    cp16(st + OFF_AHI + L.sA + ROW1_S, L.pAhi + ROW1_G);
    cp16(st + OFF_ALO + L.sA,          L.pAlo);
    cp16(st + OFF_ALO + L.sA + ROW1_S, L.pAlo + ROW1_G);
    cp16(st + OFF_BHI + L.sA,          L.pBhi);
    cp16(st + OFF_BHI + L.sA + ROW1_S, L.pBhi + ROW1_G);
    cp16(st + OFF_BLO + L.sA,          L.pBlo);
    cp16(st + OFF_BLO + L.sA + ROW1_S, L.pBlo + ROW1_G);
    L.pAhi += CHUNK_K; L.pAlo += CHUNK_K;
    L.pBhi += CHUNK_K; L.pBlo += CHUNK_K;
}

// 3-stage mainloop, unrolled by 3, single barrier + wait_group 1 per chunk.
// Exactly one commit per chunk-slot keeps the pending-group count stable.
__device__ __forceinline__ void gemm_mainloop(
    LoaderState& L, uint32_t s0, int lane, int wm, int wn, float acc[4][4][4])
{
    const uint32_t s1 = s0 + STAGE_BYTES;
    const uint32_t s2 = s0 + 2 * STAGE_BYTES;
    issue_chunk(L, s0); CP_COMMIT();
    issue_chunk(L, s1); CP_COMMIT();
    #pragma unroll 1
    for (int c = 0; c < NCHUNK; c += 3) {
        CP_WAITG1();                 // chunk c resident (c+1 may be in flight)
        __syncthreads();             // all warps past compute(c-1) in stage s2
        if (c + 2 < NCHUNK) issue_chunk(L, s2);
        CP_COMMIT();
        compute_chunk4(s0, lane, wm, wn, acc);

        CP_WAITG1();
        __syncthreads();
        if (c + 3 < NCHUNK) issue_chunk(L, s0);
        CP_COMMIT();
        compute_chunk4(s1, lane, wm, wn, acc);

        CP_WAITG1();
        __syncthreads();
        if (c + 4 < NCHUNK) issue_chunk(L, s1);
        CP_COMMIT();
        compute_chunk4(s2, lane, wm, wn, acc);
    }
}

// ---------------------------------------------------------------------------
// 1) LayerNorm + fp16 hi/lo split
// ---------------------------------------------------------------------------
__global__ void __launch_bounds__(256) ln_split_kernel(
    const float* __restrict__ h,
    const float* __restrict__ gamma,
    const float* __restrict__ beta)
{
    const int row = blockIdx.x;
    const int tid = threadIdx.x;
    const float* x = h + (size_t)row * DIM;

    float v0 = x[tid], v1 = x[tid + 256], v2 = x[tid + 512];
    float s  = v0 + v1 + v2;
    float sq = v0 * v0 + v1 * v1 + v2 * v2;
    #pragma unroll
    for (int o = 16; o > 0; o >>= 1) {
        s  += __shfl_xor_sync(0xFFFFFFFFu, s,  o);
        sq += __shfl_xor_sync(0xFFFFFFFFu, sq, o);
    }
    __shared__ float rs[8], rq[8], stat[2];
    const int warp = tid >> 5, lane = tid & 31;
    if (lane == 0) { rs[warp] = s; rq[warp] = sq; }
    __syncthreads();
    if (tid == 0) {
        float ts = 0.f, tq = 0.f;
        #pragma unroll
        for (int i = 0; i < 8; i++) { ts += rs[i]; tq += rq[i]; }
        float mean = ts * (1.0f / DIM);
        float var  = tq * (1.0f / DIM) - mean * mean;
        stat[0] = mean;
        stat[1] = rsqrtf(var + LN_EPS);
    }
    __syncthreads();
    const float mean = stat[0], rstd = stat[1];

    size_t base = (size_t)row * DIM;
    #pragma unroll
    for (int i = 0; i < 3; i++) {
        int c = tid + i * 256;
        float v = (i == 0 ? v0 : (i == 1 ? v1 : v2));
        float y = (v - mean) * rstd * gamma[c] + beta[c];
        __half hi = __float2half_rn(y);
        __half lo = __float2half_rn(y - __half2float(hi));
        g_hn_hi[base + c] = hi;
        g_hn_lo[base + c] = lo;
    }
}

// ---------------------------------------------------------------------------
// 2) Weight transpose + split
// ---------------------------------------------------------------------------
__global__ void __launch_bounds__(256) wprep_kernel(
    const float* __restrict__ wq, const float* __restrict__ wk)
{
    __shared__ float t[32][33];
    const float* W = blockIdx.z ? wk : wq;
    __half* Whi = blockIdx.z ? g_wkt_hi : g_wqt_hi;
    __half* Wlo = blockIdx.z ? g_wkt_lo : g_wqt_lo;
    const int x0 = blockIdx.x * 32, y0 = blockIdx.y * 32;
    const int tx = threadIdx.x, ty = threadIdx.y;

    for (int j = ty; j < 32; j += 8)
        t[j][tx] = W[(size_t)(y0 + j) * DIM + x0 + tx];
    __syncthreads();
    for (int j = ty; j < 32; j += 8) {
        float v = t[tx][j];
        __half hi = __float2half_rn(v);
        __half lo = __float2half_rn(v - __half2float(hi));
        size_t o = (size_t)(x0 + j) * DIM + y0 + tx;
        Whi[o] = hi;
        Wlo[o] = lo;
    }
}

// ---------------------------------------------------------------------------
// 3a) Merged Q+K projections: grid (12, 128); bx<6 -> q, else k
// ---------------------------------------------------------------------------
__global__ void __launch_bounds__(256, 2) gemm_proj(const float* __restrict__ bq,
                                                    const float* __restrict__ bk)
{
    extern __shared__ __align__(16) char smem[];
    const uint32_t sbase = cvta_s(smem);
    const int tid = threadIdx.x;
    const int wid = tid >> 5, lane = tid & 31;
    const int wm = wid >> 2, wn = wid & 3;

    const bool isK  = blockIdx.x >= 6;
    const int  nb   = isK ? (int)blockIdx.x - 6 : (int)blockIdx.x;
    const int arow0 = blockIdx.y * 128;
    const int brow0 = nb * 128;

    const __half* Bhi = isK ? g_wkt_hi : g_wqt_hi;
    const __half* Blo = isK ? g_wkt_lo : g_wqt_lo;
    const float*  bias = isK ? bk : bq;
    __half* outHi = isK ? g_k_hi : g_q_hi;
    __half* outLo = isK ? g_k_lo : g_q_lo;

    float acc[4][4][4] = {};
    LoaderState L = make_loader(tid, g_hn_hi, g_hn_lo, Bhi, Blo, arow0, brow0);
    gemm_mainloop(L, sbase, lane, wm, wn, acc);

    const int rbase = arow0 + wm * 64 + (lane >> 2);
    const int cbase = nb * 128 + wn * 32 + (lane & 3) * 2;
    #pragma unroll
    for (int mi = 0; mi < 4; mi++) {
        #pragma unroll
        for (int hm = 0; hm < 2; hm++) {
            const int r = rbase + mi * 16 + hm * 8;
            #pragma unroll
            for (int nj = 0; nj < 4; nj++) {
                const int cc = cbase + nj * 8;
                float v0 = acc[mi][nj][hm * 2 + 0] + bias[cc];
                float v1 = acc[mi][nj][hm * 2 + 1] + bias[cc + 1];
                __half h0 = __float2half_rn(v0);
                __half h1 = __float2half_rn(v1);
                __half l0 = __float2half_rn(v0 - __half2float(h0));
                __half l1 = __float2half_rn(v1 - __half2float(h1));
                size_t o = (size_t)r * DIM + cc;
                *(__half2*)&outHi[o] = __halves2half2(h0, h1);
                *(__half2*)&outLo[o] = __halves2half2(l0, l1);
            }
        }
    }
}

// ---------------------------------------------------------------------------
// 3b) Scores GEMM: grid (16, 16, 8)
// ---------------------------------------------------------------------------
__global__ void __launch_bounds__(256, 2) gemm_scores(float* __restrict__ outF)
{
    extern __shared__ __align__(16) char smem[];
    const uint32_t sbase = cvta_s(smem);
    const int tid = threadIdx.x;
    const int wid = tid >> 5, lane = tid & 31;
    const int wm = wid >> 2, wn = wid & 3;

    const int arow0 = blockIdx.z * SEQ + blockIdx.y * 128;
    const int brow0 = blockIdx.z * SEQ + blockIdx.x * 128;

    float acc[4][4][4] = {};
    LoaderState L = make_loader(tid, g_q_hi, g_q_lo, g_k_hi, g_k_lo, arow0, brow0);
    gemm_mainloop(L, sbase, lane, wm, wn, acc);

    const int rbase = arow0 + wm * 64 + (lane >> 2);
    const int cbase = blockIdx.x * 128 + wn * 32 + (lane & 3) * 2;
    #pragma unroll
    for (int mi = 0; mi < 4; mi++) {
        #pragma unroll
        for (int hm = 0; hm < 2; hm++) {
            const int r = rbase + mi * 16 + hm * 8;
            #pragma unroll
            for (int nj = 0; nj < 4; nj++) {
                const int cc = cbase + nj * 8;
                float2 v;
                v.x = acc[mi][nj][hm * 2 + 0];
                v.y = acc[mi][nj][hm * 2 + 1];
                *(float2*)&outF[(size_t)r * SEQ + cc] = v;
            }
        }
    }
}

// ---------------------------------------------------------------------------
// 4) Row softmax over 2048 columns — vectorized float4 + __expf
// ---------------------------------------------------------------------------
__global__ void __launch_bounds__(256) softmax_kernel(float* __restrict__ data)
{
    const size_t row = blockIdx.x;
    float4* p = (float4*)(data + row * (size_t)SEQ);
    const int tid = threadIdx.x;

    float4 a = p[tid];
    float4 b = p[tid + 256];
    float mx = fmaxf(fmaxf(fmaxf(a.x, a.y), fmaxf(a.z, a.w)),
                     fmaxf(fmaxf(b.x, b.y), fmaxf(b.z, b.w)));
    #pragma unroll
    for (int o = 16; o > 0; o >>= 1)
        mx = fmaxf(mx, __shfl_xor_sync(0xFFFFFFFFu, mx, o));

    __shared__ float sm[8], ss[8];
    const int warp = tid >> 5, lane = tid & 31;
    if (lane == 0) sm[warp] = mx;
    __syncthreads();
    float m = sm[0];
    #pragma unroll
    for (int i = 1; i < 8; i++) m = fmaxf(m, sm[i]);

    a.x = __expf(a.x - m); a.y = __expf(a.y - m);
    a.z = __expf(a.z - m); a.w = __expf(a.w - m);
    b.x = __expf(b.x - m); b.y = __expf(b.y - m);
    b.z = __expf(b.z - m); b.w = __expf(b.w - m);

    float s = (a.x + a.y) + (a.z + a.w) + (b.x + b.y) + (b.z + b.w);
    #pragma unroll
    for (int o = 16; o > 0; o >>= 1)
        s += __shfl_xor_sync(0xFFFFFFFFu, s, o);
    if (lane == 0) ss[warp] = s;
    __syncthreads();
    float tot = 0.f;
    #pragma unroll
    for (int i = 0; i < 8; i++) tot += ss[i];
    const float inv = 1.0f / tot;

    a.x *= inv; a.y *= inv; a.z *= inv; a.w *= inv;
    b.x *= inv; b.y *= inv; b.z *= inv; b.w *= inv;
    p[tid]       = a;
    p[tid + 256] = b;
}

// ---------------------------------------------------------------------------
// Launcher
// ---------------------------------------------------------------------------
extern "C" void kernel_launch(void* const* d_in, const int* in_sizes, int n_in,
                              void* d_out, int out_size)
{
    const float* h     = (const float*)d_in[0];
    const float* gamma = (const float*)d_in[1];
    const float* beta  = (const float*)d_in[2];
    const float* wq    = (const float*)d_in[3];
    const float* bq    = (const float*)d_in[4];
    const float* wk    = (const float*)d_in[5];
    const float* bk    = (const float*)d_in[6];
    float* out = (float*)d_out;

    cudaFuncSetAttribute(gemm_proj,   cudaFuncAttributeMaxDynamicSharedMemorySize, GEMM_SMEM);
    cudaFuncSetAttribute(gemm_scores, cudaFuncAttributeMaxDynamicSharedMemorySize, GEMM_SMEM);

    // 1) LayerNorm + split
    ln_split_kernel<<<ROWS, 256>>>(h, gamma, beta);

    // 2) Weight transpose + split
    wprep_kernel<<<dim3(24, 24, 2), dim3(32, 8)>>>(wq, wk);

    // 3) Merged Q+K projections (128x128, 2 CTAs/SM, 3-stage pipeline)
    gemm_proj<<<dim3(12, ROWS / 128), 256, GEMM_SMEM>>>(bq, bk);

    // 4) Scores (128x128, 2 CTAs/SM, 3-stage pipeline)
    gemm_scores<<<dim3(SEQ / 128, SEQ / 128, BATCH), 256, GEMM_SMEM>>>(out);

    // 5) Softmax in place
    softmax_kernel<<<ROWS, 256>>>(out);
}

// round 13
// speedup vs baseline: 1.2864x; 1.0121x over previous
#include <cuda_runtime.h>
#include <cuda_fp16.h>
#include <math.h>
#include <cstdint>

#define BATCH 8
#define SEQ   2048
#define DIM   768
#define ROWS  (BATCH * SEQ)   // 16384
#define LN_EPS 1e-5f

// ---------------------------------------------------------------------------
// Scratch (allocation-free: __device__ globals)
// ---------------------------------------------------------------------------
__device__ __half g_hn_hi[ROWS * DIM];
__device__ __half g_hn_lo[ROWS * DIM];
__device__ __half g_wqt_hi[DIM * DIM];
__device__ __half g_wqt_lo[DIM * DIM];
__device__ __half g_wkt_hi[DIM * DIM];
__device__ __half g_wkt_lo[DIM * DIM];
__device__ __half g_q_hi[ROWS * DIM];
__device__ __half g_q_lo[ROWS * DIM];
__device__ __half g_k_hi[ROWS * DIM];
__device__ __half g_k_lo[ROWS * DIM];

// ---------------------------------------------------------------------------
// PTX helpers
// ---------------------------------------------------------------------------
__device__ __forceinline__ uint32_t cvta_s(const void* p) {
    uint32_t a;
    asm("{ .reg .u64 t; cvta.to.shared.u64 t, %1; cvt.u32.u64 %0, t; }"
        : "=r"(a) : "l"(p));
    return a;
}
__device__ __forceinline__ void cp16(uint32_t dst, const void* src) {
    asm volatile("cp.async.cg.shared.global [%0], [%1], 16;" :: "r"(dst), "l"(src));
}
#define CP_COMMIT()  asm volatile("cp.async.commit_group;" ::: "memory")
#define CP_WAITG1()  asm volatile("cp.async.wait_group 1;" ::: "memory")

__device__ __forceinline__ void ldm4(uint32_t& r0, uint32_t& r1, uint32_t& r2,
                                     uint32_t& r3, uint32_t addr) {
    asm volatile("ldmatrix.sync.aligned.m8n8.x4.shared.b16 {%0,%1,%2,%3}, [%4];"
                 : "=r"(r0), "=r"(r1), "=r"(r2), "=r"(r3) : "r"(addr));
}
__device__ __forceinline__ void mma16816(float* d, const uint32_t* a,
                                         uint32_t b0, uint32_t b1) {
    asm volatile(
        "mma.sync.aligned.m16n8k16.row.col.f32.f16.f16.f32 "
        "{%0,%1,%2,%3}, {%4,%5,%6,%7}, {%8,%9}, {%0,%1,%2,%3};"
        : "+f"(d[0]), "+f"(d[1]), "+f"(d[2]), "+f"(d[3])
        : "r"(a[0]), "r"(a[1]), "r"(a[2]), "r"(a[3]), "r"(b0), "r"(b1));
}

// ---------------------------------------------------------------------------
// Tiling: CTA 128x128, 256 thr (8 warps 2x4, warp 64x32)
// Stage = Ahi, Alo, Bhi, Blo tiles of 128x32 halfs, PITCH 64B + XOR swizzle
//   smem 16B-col c' = c ^ ((row>>1)&3)
// ---------------------------------------------------------------------------
#define PITCH_B   64
#define OP_BYTES  (128 * PITCH_B)  // 8192
#define OFF_AHI  0
#define OFF_ALO  OP_BYTES
#define OFF_BHI  (2 * OP_BYTES)
#define OFF_BLO  (3 * OP_BYTES)
#define STAGE_BYTES (4 * OP_BYTES) // 32768
#define NSTAGE 3
#define GEMM_SMEM (NSTAGE * STAGE_BYTES)   // 98304
#define CHUNK_K 32
#define NCHUNK (DIM / CHUNK_K)     // 24
#define ROW1_S (64 * PITCH_B)
#define ROW1_G ((size_t)64 * DIM)

// ---------------------------------------------------------------------------
// compute one chunk; B-lo LDSM overlapped between the two b_hi MMA passes
// ---------------------------------------------------------------------------
__device__ __forceinline__ void compute_chunk4(
    uint32_t st, int lane, int wm, int wn, float acc[4][4][4])
{
    const int r16 = lane & 15;
    const int cg  = lane >> 4;
    const int sw  = (r16 >> 1) & 3;
    // per-thread row bases inside the stage (swizzle applied per-ks)
    const uint32_t aRowB = st + (uint32_t)((wm * 64 + r16) * PITCH_B);
    const uint32_t bRowB = st + (uint32_t)((wn * 32 + r16) * PITCH_B);
    #pragma unroll
    for (int ks = 0; ks < 2; ks++) {
        const uint32_t kswz = (uint32_t)((((ks * 2 + cg) ^ sw) & 3) * 16);
        const uint32_t aB = aRowB + kswz;
        const uint32_t bB = bRowB + kswz;

        // A fragments (hi + lo)
        uint32_t ah[4][4], al[4][4];
        #pragma unroll
        for (int mi = 0; mi < 4; mi++) {
            const uint32_t ad = aB + (uint32_t)(mi * 16 * PITCH_B);
            ldm4(ah[mi][0], ah[mi][1], ah[mi][2], ah[mi][3], ad + OFF_AHI);
            ldm4(al[mi][0], al[mi][1], al[mi][2], al[mi][3], ad + OFF_ALO);
        }
        // B-hi fragments
        uint32_t bh[4][2];
        #pragma unroll
        for (int nj2 = 0; nj2 < 2; nj2++) {
            const uint32_t bd = bB + OFF_BHI + (uint32_t)(nj2 * 16 * PITCH_B);
            uint32_t t0, t1, t2, t3;
            ldm4(t0, t1, t2, t3, bd);
            bh[nj2 * 2 + 0][0] = t0; bh[nj2 * 2 + 0][1] = t2;
            bh[nj2 * 2 + 1][0] = t1; bh[nj2 * 2 + 1][1] = t3;
        }
        // pass 1: ah * bh
        #pragma unroll
        for (int mi = 0; mi < 4; mi++)
            #pragma unroll
            for (int nj = 0; nj < 4; nj++)
                mma16816(acc[mi][nj], ah[mi], bh[nj][0], bh[nj][1]);
        // B-lo fragments — issued here so latency hides under pass 2
        uint32_t bl[4][2];
        #pragma unroll
        for (int nj2 = 0; nj2 < 2; nj2++) {
            const uint32_t bd = bB + OFF_BLO + (uint32_t)(nj2 * 16 * PITCH_B);
            uint32_t t0, t1, t2, t3;
            ldm4(t0, t1, t2, t3, bd);
            bl[nj2 * 2 + 0][0] = t0; bl[nj2 * 2 + 0][1] = t2;
            bl[nj2 * 2 + 1][0] = t1; bl[nj2 * 2 + 1][1] = t3;
        }
        // pass 2: al * bh
        #pragma unroll
        for (int mi = 0; mi < 4; mi++)
            #pragma unroll
            for (int nj = 0; nj < 4; nj++)
                mma16816(acc[mi][nj], al[mi], bh[nj][0], bh[nj][1]);
        // pass 3: ah * bl
        #pragma unroll
        for (int mi = 0; mi < 4; mi++)
            #pragma unroll
            for (int nj = 0; nj < 4; nj++)
                mma16816(acc[mi][nj], ah[mi], bl[nj][0], bl[nj][1]);
    }
}

// ---------------------------------------------------------------------------
// Loader: induction pointers; smem offset carries the XOR swizzle
// ---------------------------------------------------------------------------
struct LoaderState {
    const __half *pAhi, *pAlo, *pBhi, *pBlo;
    uint32_t sA;
};

__device__ __forceinline__ LoaderState make_loader(
    int tid, const __half* Ahi, const __half* Alo,
    const __half* Bhi, const __half* Blo, int arow0, int brow0)
{
    LoaderState L;
    const int row = tid >> 2;           // 0..63
    const int c   = tid & 3;
    const int cs  = c ^ ((row >> 1) & 3);
    size_t ga = (size_t)(arow0 + row) * DIM + c * 8;
    size_t gb = (size_t)(brow0 + row) * DIM + c * 8;
    L.pAhi = Ahi + ga; L.pAlo = Alo + ga;
    L.pBhi = Bhi + gb; L.pBlo = Blo + gb;
    L.sA = (uint32_t)(row * PITCH_B + cs * 16);
    return L;
}

__device__ __forceinline__ void issue_chunk(LoaderState& L, uint32_t st)
{
    cp16(st + OFF_AHI + L.sA,          L.pAhi);
    cp16(st + OFF_AHI + L.sA + ROW1_S, L.pAhi + ROW1_G);
    cp16(st + OFF_ALO + L.sA,          L.pAlo);
    cp16(st + OFF_ALO + L.sA + ROW1_S, L.pAlo + ROW1_G);
    cp16(st + OFF_BHI + L.sA,          L.pBhi);
    cp16(st + OFF_BHI + L.sA + ROW1_S, L.pBhi + ROW1_G);
    cp16(st + OFF_BLO + L.sA,          L.pBlo);
    cp16(st + OFF_BLO + L.sA + ROW1_S, L.pBlo + ROW1_G);
    L.pAhi += CHUNK_K; L.pAlo += CHUNK_K;
    L.pBhi += CHUNK_K; L.pBlo += CHUNK_K;
}

// 3-stage mainloop, unrolled by 3, wait_group 1
__device__ __forceinline__ void gemm_mainloop(
    LoaderState& L, uint32_t s0, int lane, int wm, int wn, float acc[4][4][4])
{
    const uint32_t s1 = s0 + STAGE_BYTES;
    const uint32_t s2 = s0 + 2 * STAGE_BYTES;
    issue_chunk(L, s0); CP_COMMIT();
    issue_chunk(L, s1); CP_COMMIT();
    #pragma unroll 1
    for (int c = 0; c < NCHUNK; c += 3) {
        CP_WAITG1();
        __syncthreads();
        if (c + 2 < NCHUNK) issue_chunk(L, s2);
        CP_COMMIT();
        compute_chunk4(s0, lane, wm, wn, acc);

        CP_WAITG1();
        __syncthreads();
        if (c + 3 < NCHUNK) issue_chunk(L, s0);
        CP_COMMIT();
        compute_chunk4(s1, lane, wm, wn, acc);

        CP_WAITG1();
        __syncthreads();
        if (c + 4 < NCHUNK) issue_chunk(L, s1);
        CP_COMMIT();
        compute_chunk4(s2, lane, wm, wn, acc);
    }
}

// ---------------------------------------------------------------------------
// 1) LayerNorm + fp16 hi/lo split — float4 loads, half2 stores (192 thr)
// ---------------------------------------------------------------------------
__global__ void __launch_bounds__(192) ln_split_kernel(
    const float* __restrict__ h,
    const float* __restrict__ gamma,
    const float* __restrict__ beta)
{
    const int row = blockIdx.x;
    const int tid = threadIdx.x;                  // 0..191, 4 cols each
    const float4* x4 = (const float4*)(h + (size_t)row * DIM);

    float4 v = x4[tid];
    float s  = (v.x + v.y) + (v.z + v.w);
    float sq = (v.x * v.x + v.y * v.y) + (v.z * v.z + v.w * v.w);
    #pragma unroll
    for (int o = 16; o > 0; o >>= 1) {
        s  += __shfl_xor_sync(0xFFFFFFFFu, s,  o);
        sq += __shfl_xor_sync(0xFFFFFFFFu, sq, o);
    }
    __shared__ float rs[6], rq[6], stat[2];
    const int warp = tid >> 5, lane = tid & 31;
    if (lane == 0) { rs[warp] = s; rq[warp] = sq; }
    __syncthreads();
    if (tid == 0) {
        float ts = 0.f, tq = 0.f;
        #pragma unroll
        for (int i = 0; i < 6; i++) { ts += rs[i]; tq += rq[i]; }
        float mean = ts * (1.0f / DIM);
        float var  = tq * (1.0f / DIM) - mean * mean;
        stat[0] = mean;
        stat[1] = rsqrtf(var + LN_EPS);
    }
    __syncthreads();
    const float mean = stat[0], rstd = stat[1];

    const float4 g4 = ((const float4*)gamma)[tid];
    const float4 b4 = ((const float4*)beta)[tid];
    float y0 = (v.x - mean) * rstd * g4.x + b4.x;
    float y1 = (v.y - mean) * rstd * g4.y + b4.y;
    float y2 = (v.z - mean) * rstd * g4.z + b4.z;
    float y3 = (v.w - mean) * rstd * g4.w + b4.w;

    __half h0 = __float2half_rn(y0), h1 = __float2half_rn(y1);
    __half h2 = __float2half_rn(y2), h3 = __float2half_rn(y3);
    __half l0 = __float2half_rn(y0 - __half2float(h0));
    __half l1 = __float2half_rn(y1 - __half2float(h1));
    __half l2 = __float2half_rn(y2 - __half2float(h2));
    __half l3 = __float2half_rn(y3 - __half2float(h3));

    size_t base = (size_t)row * DIM + tid * 4;
    *(__half2*)&g_hn_hi[base]     = __halves2half2(h0, h1);
    *(__half2*)&g_hn_hi[base + 2] = __halves2half2(h2, h3);
    *(__half2*)&g_hn_lo[base]     = __halves2half2(l0, l1);
    *(__half2*)&g_hn_lo[base + 2] = __halves2half2(l2, l3);
}

// ---------------------------------------------------------------------------
// 2) Weight transpose + split
// ---------------------------------------------------------------------------
__global__ void __launch_bounds__(256) wprep_kernel(
    const float* __restrict__ wq, const float* __restrict__ wk)
{
    __shared__ float t[32][33];
    const float* W = blockIdx.z ? wk : wq;
    __half* Whi = blockIdx.z ? g_wkt_hi : g_wqt_hi;
    __half* Wlo = blockIdx.z ? g_wkt_lo : g_wqt_lo;
    const int x0 = blockIdx.x * 32, y0 = blockIdx.y * 32;
    const int tx = threadIdx.x, ty = threadIdx.y;

    for (int j = ty; j < 32; j += 8)
        t[j][tx] = W[(size_t)(y0 + j) * DIM + x0 + tx];
    __syncthreads();
    for (int j = ty; j < 32; j += 8) {
        float v = t[tx][j];
        __half hi = __float2half_rn(v);
        __half lo = __float2half_rn(v - __half2float(hi));
        size_t o = (size_t)(x0 + j) * DIM + y0 + tx;
        Whi[o] = hi;
        Wlo[o] = lo;
    }
}

// ---------------------------------------------------------------------------
// 3a) Merged Q+K projections: grid (12, 128); bx<6 -> q, else k
// ---------------------------------------------------------------------------
__global__ void __launch_bounds__(256, 2) gemm_proj(const float* __restrict__ bq,
                                                    const float* __restrict__ bk)
{
    extern __shared__ __align__(16) char smem[];
    const uint32_t sbase = cvta_s(smem);
    const int tid = threadIdx.x;
    const int wid = tid >> 5, lane = tid & 31;
    const int wm = wid >> 2, wn = wid & 3;

    const bool isK  = blockIdx.x >= 6;
    const int  nb   = isK ? (int)blockIdx.x - 6 : (int)blockIdx.x;
    const int arow0 = blockIdx.y * 128;
    const int brow0 = nb * 128;

    const __half* Bhi = isK ? g_wkt_hi : g_wqt_hi;
    const __half* Blo = isK ? g_wkt_lo : g_wqt_lo;
    const float*  bias = isK ? bk : bq;
    __half* outHi = isK ? g_k_hi : g_q_hi;
    __half* outLo = isK ? g_k_lo : g_q_lo;

    float acc[4][4][4] = {};
    LoaderState L = make_loader(tid, g_hn_hi, g_hn_lo, Bhi, Blo, arow0, brow0);
    gemm_mainloop(L, sbase, lane, wm, wn, acc);

    const int rbase = arow0 + wm * 64 + (lane >> 2);
    const int cbase = nb * 128 + wn * 32 + (lane & 3) * 2;
    #pragma unroll
    for (int mi = 0; mi < 4; mi++) {
        #pragma unroll
        for (int hm = 0; hm < 2; hm++) {
            const int r = rbase + mi * 16 + hm * 8;
            #pragma unroll
            for (int nj = 0; nj < 4; nj++) {
                const int cc = cbase + nj * 8;
                float v0 = acc[mi][nj][hm * 2 + 0] + bias[cc];
                float v1 = acc[mi][nj][hm * 2 + 1] + bias[cc + 1];
                __half h0 = __float2half_rn(v0);
                __half h1 = __float2half_rn(v1);
                __half l0 = __float2half_rn(v0 - __half2float(h0));
                __half l1 = __float2half_rn(v1 - __half2float(h1));
                size_t o = (size_t)r * DIM + cc;
                *(__half2*)&outHi[o] = __halves2half2(h0, h1);
                *(__half2*)&outLo[o] = __halves2half2(l0, l1);
            }
        }
    }
}

// ---------------------------------------------------------------------------
// 3b) Scores GEMM: grid (16, 16, 8)
// ---------------------------------------------------------------------------
__global__ void __launch_bounds__(256, 2) gemm_scores(float* __restrict__ outF)
{
    extern __shared__ __align__(16) char smem[];
    const uint32_t sbase = cvta_s(smem);
    const int tid = threadIdx.x;
    const int wid = tid >> 5, lane = tid & 31;
    const int wm = wid >> 2, wn = wid & 3;

    const int arow0 = blockIdx.z * SEQ + blockIdx.y * 128;
    const int brow0 = blockIdx.z * SEQ + blockIdx.x * 128;

    float acc[4][4][4] = {};
    LoaderState L = make_loader(tid, g_q_hi, g_q_lo, g_k_hi, g_k_lo, arow0, brow0);
    gemm_mainloop(L, sbase, lane, wm, wn, acc);

    const int rbase = arow0 + wm * 64 + (lane >> 2);
    const int cbase = blockIdx.x * 128 + wn * 32 + (lane & 3) * 2;
    #pragma unroll
    for (int mi = 0; mi < 4; mi++) {
        #pragma unroll
        for (int hm = 0; hm < 2; hm++) {
            const int r = rbase + mi * 16 + hm * 8;
            #pragma unroll
            for (int nj = 0; nj < 4; nj++) {
                const int cc = cbase + nj * 8;
                float2 v;
                v.x = acc[mi][nj][hm * 2 + 0];
                v.y = acc[mi][nj][hm * 2 + 1];
                *(float2*)&outF[(size_t)r * SEQ + cc] = v;
            }
        }
    }
}

// ---------------------------------------------------------------------------
// 4) Row softmax over 2048 columns — float4 + __expf
// ---------------------------------------------------------------------------
__global__ void __launch_bounds__(256) softmax_kernel(float* __restrict__ data)
{
    const size_t row = blockIdx.x;
    float4* p = (float4*)(data + row * (size_t)SEQ);
    const int tid = threadIdx.x;

    float4 a = p[tid];
    float4 b = p[tid + 256];
    float mx = fmaxf(fmaxf(fmaxf(a.x, a.y), fmaxf(a.z, a.w)),
                     fmaxf(fmaxf(b.x, b.y), fmaxf(b.z, b.w)));
    #pragma unroll
    for (int o = 16; o > 0; o >>= 1)
        mx = fmaxf(mx, __shfl_xor_sync(0xFFFFFFFFu, mx, o));

    __shared__ float sm[8], ss[8];
    const int warp = tid >> 5, lane = tid & 31;
    if (lane == 0) sm[warp] = mx;
    __syncthreads();
    float m = sm[0];
    #pragma unroll
    for (int i = 1; i < 8; i++) m = fmaxf(m, sm[i]);

    a.x = __expf(a.x - m); a.y = __expf(a.y - m);
    a.z = __expf(a.z - m); a.w = __expf(a.w - m);
    b.x = __expf(b.x - m); b.y = __expf(b.y - m);
    b.z = __expf(b.z - m); b.w = __expf(b.w - m);

    float s = (a.x + a.y) + (a.z + a.w) + (b.x + b.y) + (b.z + b.w);
    #pragma unroll
    for (int o = 16; o > 0; o >>= 1)
        s += __shfl_xor_sync(0xFFFFFFFFu, s, o);
    if (lane == 0) ss[warp] = s;
    __syncthreads();
    float tot = 0.f;
    #pragma unroll
    for (int i = 0; i < 8; i++) tot += ss[i];
    const float inv = 1.0f / tot;

    a.x *= inv; a.y *= inv; a.z *= inv; a.w *= inv;
    b.x *= inv; b.y *= inv; b.z *= inv; b.w *= inv;
    p[tid]       = a;
    p[tid + 256] = b;
}

// ---------------------------------------------------------------------------
// Launcher
// ---------------------------------------------------------------------------
extern "C" void kernel_launch(void* const* d_in, const int* in_sizes, int n_in,
                              void* d_out, int out_size)
{
    const float* h     = (const float*)d_in[0];
    const float* gamma = (const float*)d_in[1];
    const float* beta  = (const float*)d_in[2];
    const float* wq    = (const float*)d_in[3];
    const float* bq    = (const float*)d_in[4];
    const float* wk    = (const float*)d_in[5];
    const float* bk    = (const float*)d_in[6];
    float* out = (float*)d_out;

    cudaFuncSetAttribute(gemm_proj,   cudaFuncAttributeMaxDynamicSharedMemorySize, GEMM_SMEM);
    cudaFuncSetAttribute(gemm_scores, cudaFuncAttributeMaxDynamicSharedMemorySize, GEMM_SMEM);

    // 1) LayerNorm + split
    ln_split_kernel<<<ROWS, 192>>>(h, gamma, beta);

    // 2) Weight transpose + split
    wprep_kernel<<<dim3(24, 24, 2), dim3(32, 8)>>>(wq, wk);

    // 3) Merged Q+K projections (128x128, 2 CTAs/SM, 3-stage)
    gemm_proj<<<dim3(12, ROWS / 128), 256, GEMM_SMEM>>>(bq, bk);

    // 4) Scores (128x128, 2 CTAs/SM, 3-stage)
    gemm_scores<<<dim3(SEQ / 128, SEQ / 128, BATCH), 256, GEMM_SMEM>>>(out);

    // 5) Softmax in place
    softmax_kernel<<<ROWS, 256>>>(out);
}